// round 17
// baseline (speedup 1.0000x reference)
#include <cuda_runtime.h>

#define BATCH  16384
#define NNZ    819200
#define KDIM   16
#define VOCAB  1000000
#define RPW    2          // rows per warp (consecutive -> contiguous nnz)
#define CAP    160        // staged nnz per chunk (pair span ~100, max ~145)

__device__ int g_row_ptr[BATCH + 1];
__device__ int g_is64;

// ---------------------------------------------------------------------------
// dtype detection: words 2i+1 (i < NNZ/2) are in-bounds under both views.
// int64 view -> high words all 0; int32 view -> sorted index vals ~8191 != 0.
// ---------------------------------------------------------------------------
__device__ __forceinline__ int detect_is64(const unsigned int* __restrict__ w) {
    unsigned int acc = 0;
    int base = NNZ / 2 - 8;
#pragma unroll
    for (int i = 0; i < 8; i++) acc |= w[2 * (base + i) + 1];
    return (acc == 0u) ? 1 : 0;
}

template <bool IS64>
__device__ __forceinline__ int ld_i(const void* __restrict__ p, int i) {
    if (IS64) return (int)__ldcs((const long long*)p + i);
    return __ldcs((const int*)p + i);
}

// ---------------------------------------------------------------------------
// K1: rowptr via adjacent difference over the sorted index (proven ~1 us).
// ---------------------------------------------------------------------------
__global__ void __launch_bounds__(256)
rowptr_kernel(const void* __restrict__ index) {
    __shared__ int s_is64;
    if (threadIdx.x == 0) {
        int is64 = detect_is64((const unsigned int*)index);
        s_is64 = is64;
        if (blockIdx.x == 0) g_is64 = is64;
    }
    __syncthreads();
    const int is64 = s_is64;

    const int i = blockIdx.x * blockDim.x + threadIdx.x;
    if (i >= NNZ) return;

    int a, b;
    if (is64) {
        a = ld_i<true >(index, i);
        b = (i + 1 < NNZ) ? ld_i<true >(index, i + 1) : BATCH;
    } else {
        a = ld_i<false>(index, i);
        b = (i + 1 < NNZ) ? ld_i<false>(index, i + 1) : BATCH;
    }
    if (i == 0)
        for (int r = 0; r <= a; r++) g_row_ptr[r] = 0;
    for (int r = a + 1; r <= b; r++) g_row_ptr[r] = i + 1;
}

// ---------------------------------------------------------------------------
// K2: warp per 2 consecutive rows (contiguous nnz span).
//  Stage: flattened 5-slot form (CAP=160) -- all feats/values loads issue
//    back-to-back, then 5 independent weights loads, then unconditional smem
//    stores, and the first-order FMA chains last (per-row via slot masks).
//  Gather per row: octet layout (8 groups g x 4 slots m); LDS.64 broadcast +
//    embedding LDG.128; independent iterations, unroll 4.
//  One merged epilogue for both rows.
// ---------------------------------------------------------------------------
struct __align__(16) WBuf { float2 fv[CAP]; };   // 1280 B/warp

__device__ __forceinline__ float fo_term(int o, int lim0, int lim1,
                                         float w, float v, float& fb) {
    // returns contribution to row0's first-order; adds row1's into fb.
    // slot covers row0 iff o < lim0, row1 iff lim0 <= o < lim1 (w,v are 0 past n)
    if (o < lim0) return w * v;
    if (o < lim1) fb = fmaf(w, v, fb);
    return 0.f;
}

template <bool IS64>
__device__ __forceinline__ void fm_pair(
        int b0, int lane, WBuf* __restrict__ buf,
        const void* __restrict__ feats,
        const float* __restrict__ values,
        const float* __restrict__ weights,
        const float* __restrict__ embedding,
        float bias_v, float* __restrict__ out) {
    const int g = lane >> 2;   // octet position 0..7
    const int m = lane & 3;    // float4 slot: k = 4m .. 4m+3

    int se = 0;
    if (lane <= RPW) se = __ldg(&g_row_ptr[b0 + lane]);
    const int s0 = __shfl_sync(0xffffffffu, se, 0);
    const int s1 = __shfl_sync(0xffffffffu, se, 1);
    const int s2 = __shfl_sync(0xffffffffu, se, 2);

    float4 t1a = make_float4(0.f, 0.f, 0.f, 0.f);
    float4 t1b = make_float4(0.f, 0.f, 0.f, 0.f);
    float  t2a = 0.f, t2b = 0.f, fia = 0.f, fib = 0.f;

    for (int cb = s0; cb < s2; cb += CAP) {
        const int n    = min(s2 - cb, CAP);
        const int lim0 = s1 - cb;   // slots < lim0 belong to row 0

        // ---- stage: flattened 5-slot form, loads first, FMAs last ----
        int   f[5];
        float v[5], w[5];
#pragma unroll
        for (int t = 0; t < 5; t++) {
            const int o = lane + 32 * t;
            f[t] = 0; v[t] = 0.f;
            if (o < n) { f[t] = ld_i<IS64>(feats, cb + o); v[t] = __ldcs(values + cb + o); }
        }
#pragma unroll
        for (int t = 0; t < 5; t++) {
            const int o = lane + 32 * t;
            w[t] = 0.f;
            if (o < n) w[t] = __ldg(weights + f[t]);
        }
#pragma unroll
        for (int t = 0; t < 5; t++)
            buf->fv[lane + 32 * t] = make_float2(__int_as_float(f[t] * KDIM), v[t]);
        __syncwarp();

        // first-order FMAs (never gate issue; consumed only at epilogue)
#pragma unroll
        for (int t = 0; t < 5; t++)
            fia += fo_term(lane + 32 * t, lim0, n, w[t], v[t], fib);

        // ---- gather row 0 slice [0, min(lim0, n)) ----
        {
            const int re = min(lim0, n);
#pragma unroll 4
            for (int t = 0; t < (re + 7) / 8; t++) {
                const int j  = 8 * t + g;
                const int jc = (j < re) ? j : (re - 1);
                const float2 fv = buf->fv[jc];
                const int    fr = __float_as_int(fv.x);
                const float  vv = (j < re) ? fv.y : 0.f;
                const float4 e4 = __ldg((const float4*)(embedding + fr) + m);
                const float e0 = e4.x * vv, e1 = e4.y * vv,
                            e2 = e4.z * vv, e3 = e4.w * vv;
                t1a.x += e0; t1a.y += e1; t1a.z += e2; t1a.w += e3;
                t2a = fmaf(e0, e0, t2a); t2a = fmaf(e1, e1, t2a);
                t2a = fmaf(e2, e2, t2a); t2a = fmaf(e3, e3, t2a);
            }
        }
        // ---- gather row 1 slice [max(lim0,0), n) ----
        {
            const int rs = (lim0 > 0) ? lim0 : 0;
#pragma unroll 4
            for (int t = 0; t < (n - rs + 7) / 8; t++) {
                const int j  = rs + 8 * t + g;
                const int jc = (j < n) ? j : (n - 1);
                const float2 fv = buf->fv[jc];
                const int    fr = __float_as_int(fv.x);
                const float  vv = (j < n) ? fv.y : 0.f;
                const float4 e4 = __ldg((const float4*)(embedding + fr) + m);
                const float e0 = e4.x * vv, e1 = e4.y * vv,
                            e2 = e4.z * vv, e3 = e4.w * vv;
                t1b.x += e0; t1b.y += e1; t1b.z += e2; t1b.w += e3;
                t2b = fmaf(e0, e0, t2b); t2b = fmaf(e1, e1, t2b);
                t2b = fmaf(e2, e2, t2b); t2b = fmaf(e3, e3, t2b);
            }
        }
        __syncwarp();
    }

    // ---- merged epilogue: octet combine (lane bits 2..4), then warp sums ----
#pragma unroll
    for (int o = 4; o <= 16; o <<= 1) {
        t1a.x += __shfl_xor_sync(0xffffffffu, t1a.x, o);
        t1a.y += __shfl_xor_sync(0xffffffffu, t1a.y, o);
        t1a.z += __shfl_xor_sync(0xffffffffu, t1a.z, o);
        t1a.w += __shfl_xor_sync(0xffffffffu, t1a.w, o);
        t1b.x += __shfl_xor_sync(0xffffffffu, t1b.x, o);
        t1b.y += __shfl_xor_sync(0xffffffffu, t1b.y, o);
        t1b.z += __shfl_xor_sync(0xffffffffu, t1b.z, o);
        t1b.w += __shfl_xor_sync(0xffffffffu, t1b.w, o);
    }
    // |t1|^2 replicated 8x across g-groups -> coefficient 0.5/8 = 0.0625
    float ra = 0.0625f * (t1a.x * t1a.x + t1a.y * t1a.y + t1a.z * t1a.z + t1a.w * t1a.w)
             - 0.5f * t2a + fia;
    float rb = 0.0625f * (t1b.x * t1b.x + t1b.y * t1b.y + t1b.z * t1b.z + t1b.w * t1b.w)
             - 0.5f * t2b + fib;
#pragma unroll
    for (int o = 16; o > 0; o >>= 1) {
        ra += __shfl_xor_sync(0xffffffffu, ra, o);
        rb += __shfl_xor_sync(0xffffffffu, rb, o);
    }

    if (lane == 0) {
        out[b0]     = 1.0f / (1.0f + expf(-(ra + bias_v)));
        out[b0 + 1] = 1.0f / (1.0f + expf(-(rb + bias_v)));
    }
}

__global__ void __launch_bounds__(256)
fm_kernel(const void* __restrict__ feats,
          const float* __restrict__ values,
          const float* __restrict__ weights,
          const float* __restrict__ embedding,
          const float* __restrict__ bias,
          float* __restrict__ out) {
    __shared__ WBuf bufs[8];

    const int warp = (blockIdx.x * blockDim.x + threadIdx.x) >> 5;
    const int lane = threadIdx.x & 31;
    if (warp >= BATCH / RPW) return;
    WBuf* buf = &bufs[threadIdx.x >> 5];
    const float bias_v = __ldg(bias);

    if (g_is64) fm_pair<true >(warp * RPW, lane, buf, feats, values, weights, embedding, bias_v, out);
    else        fm_pair<false>(warp * RPW, lane, buf, feats, values, weights, embedding, bias_v, out);
}

// ---------------------------------------------------------------------------
extern "C" void kernel_launch(void* const* d_in, const int* in_sizes, int n_in,
                              void* d_out, int out_size) {
    const void*  index_p   = nullptr;
    const void*  feats_p   = nullptr;
    const float* values_p  = nullptr;
    const float* bias_p    = nullptr;
    const float* weights_p = nullptr;
    const float* embed_p   = nullptr;

    int triple = 0;
    for (int i = 0; i < n_in; i++) {
        int sz = in_sizes[i];
        if (sz == NNZ) {
            if      (triple == 0) index_p  = d_in[i];
            else if (triple == 1) feats_p  = d_in[i];
            else                  values_p = (const float*)d_in[i];
            triple++;
        } else if (sz == VOCAB) {
            weights_p = (const float*)d_in[i];
        } else if (sz == VOCAB * KDIM) {
            embed_p = (const float*)d_in[i];
        } else if (sz == 1) {
            bias_p = (const float*)d_in[i];   // last size-1 input is bias
        }
    }

    float* out = (float*)d_out;
    (void)out_size;

    rowptr_kernel<<<(NNZ + 255) / 256, 256>>>(index_p);
    fm_kernel<<<((BATCH / RPW) * 32 + 255) / 256, 256>>>(feats_p, values_p,
                                                         weights_p, embed_p,
                                                         bias_p, out);
}